// round 1
// baseline (speedup 1.0000x reference)
#include <cuda_runtime.h>
#include <cuda_bf16.h>
#include <cstdint>

#define NUM_CLASSES 1000
#define FEAT_DIM    256
#define K_PER_IMG   100

// -------- persistent scratch (no allocations allowed) --------
__device__ float              g_sums[NUM_CLASSES * FEAT_DIM]; // per-class feature sums
__device__ float              g_counts[NUM_CLASSES];          // per-class counts
__device__ unsigned long long g_mask[NUM_CLASSES];            // per-class image-presence bitmask (B<=64)

// ---------------- K0: zero scratch ----------------
__global__ void zero_scratch_kernel() {
    int idx = blockIdx.x * blockDim.x + threadIdx.x;
    if (idx < NUM_CLASSES * FEAT_DIM) g_sums[idx] = 0.0f;
    if (idx < NUM_CLASSES) {
        g_counts[idx] = 0.0f;
        g_mask[idx]   = 0ULL;
    }
}

// ---------------- K1: normalize rows + scatter into class sums ----------------
// One warp per row. Each lane owns 8 consecutive floats (2x float4).
__global__ void normalize_scatter_kernel(const float* __restrict__ features,
                                         const int*   __restrict__ labels,
                                         int n_rows) {
    int gwarp = (blockIdx.x * blockDim.x + threadIdx.x) >> 5;
    int lane  = threadIdx.x & 31;
    if (gwarp >= n_rows) return;

    const float4* row = reinterpret_cast<const float4*>(features + (size_t)gwarp * FEAT_DIM);
    float4 a = __ldg(row + lane * 2);
    float4 b = __ldg(row + lane * 2 + 1);

    float ss = a.x * a.x + a.y * a.y + a.z * a.z + a.w * a.w
             + b.x * b.x + b.y * b.y + b.z * b.z + b.w * b.w;
    #pragma unroll
    for (int off = 16; off > 0; off >>= 1)
        ss += __shfl_xor_sync(0xFFFFFFFFu, ss, off);

    float inv = 1.0f / fmaxf(sqrtf(ss), 1e-12f);

    a.x *= inv; a.y *= inv; a.z *= inv; a.w *= inv;
    b.x *= inv; b.y *= inv; b.z *= inv; b.w *= inv;

    int lbl = __ldg(labels + gwarp);
    float* dst = g_sums + lbl * FEAT_DIM + lane * 8;

    // vector reduction (no return) — sm_90+ red.global.add.v4.f32
    asm volatile("red.global.add.v4.f32 [%0], {%1,%2,%3,%4};"
                 :: "l"(dst), "f"(a.x), "f"(a.y), "f"(a.z), "f"(a.w) : "memory");
    asm volatile("red.global.add.v4.f32 [%0], {%1,%2,%3,%4};"
                 :: "l"(dst + 4), "f"(b.x), "f"(b.y), "f"(b.z), "f"(b.w) : "memory");

    if (lane == 0) atomicAdd(&g_counts[lbl], 1.0f);
}

// ---------------- K2: presence bitmask from labels_per_image ----------------
__global__ void build_mask_kernel(const int* __restrict__ lpi, int n_elems) {
    int idx = blockIdx.x * blockDim.x + threadIdx.x;
    if (idx >= n_elems) return;
    int b   = idx / K_PER_IMG;              // image index (0..63)
    int lbl = __ldg(lpi + idx);
    atomicOr(&g_mask[lbl], 1ULL << b);
}

// ---------------- K3: prototype EMA + init flag ----------------
__global__ void proto_update_kernel(const float* __restrict__ prototypes,
                                    const int*   __restrict__ init_mask,
                                    const int*   __restrict__ step_ptr,
                                    float*       __restrict__ out_protos,   // [1000*256]
                                    float*       __restrict__ out_init) {   // [1000]
    int c = blockIdx.x;
    int d = threadIdx.x;

    float stepf    = step_ptr ? (float)__ldg(step_ptr) : 5000.0f;
    float progress = fminf(1.0f, stepf / 2000.0f);          // WARMUP_STEPS*10
    float m        = 0.99f + (0.999f - 0.99f) * progress;

    float cnt     = g_counts[c];
    bool  present = cnt > 0.0f;
    bool  inited  = __ldg(init_mask + c) > 0;

    float mean = g_sums[c * FEAT_DIM + d] / fmaxf(cnt, 1.0f);
    float p    = __ldg(prototypes + c * FEAT_DIM + d);

    float val;
    if (present && inited)       val = m * p + (1.0f - m) * mean;
    else if (present)            val = mean;
    else                         val = p;

    out_protos[c * FEAT_DIM + d] = val;
    if (d == 0) out_init[c] = (inited || present) ? 1.0f : 0.0f;
}

// ---------------- K4: co-occurrence via popcount of bitmasks ----------------
__global__ void cooc_kernel(const float* __restrict__ cooc_in,
                            float*       __restrict__ cooc_out) {
    int idx = blockIdx.x * blockDim.x + threadIdx.x;
    if (idx >= NUM_CLASSES * NUM_CLASSES) return;
    int i = idx / NUM_CLASSES;
    int j = idx - i * NUM_CLASSES;
    float add = (i == j) ? 0.0f
              : (float)__popcll(__ldg(&g_mask[i]) & __ldg(&g_mask[j]));
    cooc_out[idx] = __ldg(cooc_in + idx) + add;
}

// ---------------- launch ----------------
extern "C" void kernel_launch(void* const* d_in, const int* in_sizes, int n_in,
                              void* d_out, int out_size) {
    const float* features  = (const float*)d_in[0];
    const int*   labels    = (const int*)  d_in[1];
    const int*   lpi       = (const int*)  d_in[2];
    const float* protos    = (const float*)d_in[3];
    const int*   init_mask = (const int*)  d_in[4];
    const float* cooc_in   = (const float*)d_in[5];
    const int*   step_ptr  = (n_in > 6) ? (const int*)d_in[6] : nullptr;

    int n_rows  = in_sizes[1];   // 200000
    int n_lpi   = in_sizes[2];   // 64*100

    float* out        = (float*)d_out;
    float* out_protos = out;                                          // 256000
    float* out_init   = out + NUM_CLASSES * FEAT_DIM;                 // 1000
    float* out_cooc   = out + NUM_CLASSES * FEAT_DIM + NUM_CLASSES;   // 1000000

    // K0: zero scratch
    {
        int tot = NUM_CLASSES * FEAT_DIM;
        zero_scratch_kernel<<<(tot + 255) / 256, 256>>>();
    }
    // K1: heavy pass — warp per row
    {
        int total_threads = n_rows * 32;
        normalize_scatter_kernel<<<(total_threads + 255) / 256, 256>>>(features, labels, n_rows);
    }
    // K2: presence masks
    build_mask_kernel<<<(n_lpi + 255) / 256, 256>>>(lpi, n_lpi);
    // K3: prototype EMA (1000 blocks x 256 threads)
    proto_update_kernel<<<NUM_CLASSES, FEAT_DIM>>>(protos, init_mask, step_ptr,
                                                   out_protos, out_init);
    // K4: co-occurrence
    {
        int tot = NUM_CLASSES * NUM_CLASSES;
        cooc_kernel<<<(tot + 255) / 256, 256>>>(cooc_in, out_cooc);
    }
}

// round 3
// speedup vs baseline: 1.1183x; 1.1183x over previous
#include <cuda_runtime.h>
#include <cuda_bf16.h>
#include <cstdint>

#define NUM_CLASSES 1000
#define FEAT_DIM    256
#define K_PER_IMG   100
#define MAX_ROWS    200704

// -------- persistent scratch (no device allocations allowed) --------
__device__ int                g_hist[NUM_CLASSES];    // per-class row count
__device__ int                g_off[NUM_CLASSES];     // exclusive prefix (segment start)
__device__ int                g_cursor[NUM_CLASSES];  // scatter cursors
__device__ int                g_order[MAX_ROWS];      // row indices grouped by class
__device__ unsigned long long g_mask[NUM_CLASSES];    // per-class image-presence bitmask (B<=64)

// ---------------- K0: zero small scratch ----------------
__global__ void zero_scratch_kernel() {
    int idx = blockIdx.x * blockDim.x + threadIdx.x;
    if (idx < NUM_CLASSES) {
        g_hist[idx] = 0;
        g_mask[idx] = 0ULL;
    }
}

// ---------------- K1a: label histogram (smem-privatized) ----------------
__global__ void hist_kernel(const int* __restrict__ labels, int n) {
    __shared__ int sh[NUM_CLASSES];
    for (int i = threadIdx.x; i < NUM_CLASSES; i += blockDim.x) sh[i] = 0;
    __syncthreads();
    for (int i = blockIdx.x * blockDim.x + threadIdx.x; i < n; i += gridDim.x * blockDim.x)
        atomicAdd(&sh[__ldg(labels + i)], 1);
    __syncthreads();
    for (int i = threadIdx.x; i < NUM_CLASSES; i += blockDim.x) {
        int v = sh[i];
        if (v) atomicAdd(&g_hist[i], v);
    }
}

// ---------------- K1b: exclusive prefix scan over 1000 counts (1 block) ----------------
__global__ void scan_kernel() {
    __shared__ int sh[1024];
    int t = threadIdx.x;
    int v = (t < NUM_CLASSES) ? g_hist[t] : 0;
    sh[t] = v;
    __syncthreads();
    #pragma unroll
    for (int off = 1; off < 1024; off <<= 1) {
        int x = (t >= off) ? sh[t - off] : 0;
        __syncthreads();
        sh[t] += x;
        __syncthreads();
    }
    if (t < NUM_CLASSES) {
        int excl = sh[t] - v;
        g_off[t]    = excl;
        g_cursor[t] = excl;
    }
}

// ---------------- K1c: scatter row indices into class-grouped order ----------------
__global__ void scatter_kernel(const int* __restrict__ labels, int n) {
    int i = blockIdx.x * blockDim.x + threadIdx.x;
    if (i >= n) return;
    int l = __ldg(labels + i);
    int p = atomicAdd(&g_cursor[l], 1);
    g_order[p] = i;
}

// ---------------- K2: presence bitmask from labels_per_image ----------------
__global__ void build_mask_kernel(const int* __restrict__ lpi, int n_elems) {
    int idx = blockIdx.x * blockDim.x + threadIdx.x;
    if (idx >= n_elems) return;
    int b   = idx / K_PER_IMG;
    int lbl = __ldg(lpi + idx);
    atomicOr(&g_mask[lbl], 1ULL << b);
}

// ---------------- K3: per-class gather-reduce + fused prototype EMA ----------------
// One block (256 thr = 8 warps) per class. Each warp streams whole 1KB rows
// of its class (2x float4 per lane), 2 rows in flight for MLP. No atomics.
__global__ void __launch_bounds__(256) class_reduce_kernel(
        const float* __restrict__ features,
        const float* __restrict__ prototypes,
        const int*   __restrict__ init_mask,
        const int*   __restrict__ step_ptr,
        float*       __restrict__ out_protos,   // [1000*256]
        float*       __restrict__ out_init) {   // [1000]
    int c     = blockIdx.x;
    int warp  = threadIdx.x >> 5;
    int lane  = threadIdx.x & 31;
    int start = g_off[c];
    int cnt   = g_hist[c];

    float acc[8] = {0.f, 0.f, 0.f, 0.f, 0.f, 0.f, 0.f, 0.f};

    int r = warp;
    // 2-row unrolled main loop: 4 independent LDG.128 batched up front
    for (; r + 8 < cnt; r += 16) {
        int row0 = __ldg(g_order + start + r);
        int row1 = __ldg(g_order + start + r + 8);
        const float4* rp0 = reinterpret_cast<const float4*>(features + (size_t)row0 * FEAT_DIM);
        const float4* rp1 = reinterpret_cast<const float4*>(features + (size_t)row1 * FEAT_DIM);
        float4 a0 = __ldg(rp0 + lane * 2);
        float4 b0 = __ldg(rp0 + lane * 2 + 1);
        float4 a1 = __ldg(rp1 + lane * 2);
        float4 b1 = __ldg(rp1 + lane * 2 + 1);

        float ss0 = a0.x*a0.x + a0.y*a0.y + a0.z*a0.z + a0.w*a0.w
                  + b0.x*b0.x + b0.y*b0.y + b0.z*b0.z + b0.w*b0.w;
        float ss1 = a1.x*a1.x + a1.y*a1.y + a1.z*a1.z + a1.w*a1.w
                  + b1.x*b1.x + b1.y*b1.y + b1.z*b1.z + b1.w*b1.w;
        #pragma unroll
        for (int off = 16; off > 0; off >>= 1) {
            ss0 += __shfl_xor_sync(0xFFFFFFFFu, ss0, off);
            ss1 += __shfl_xor_sync(0xFFFFFFFFu, ss1, off);
        }
        float inv0 = 1.0f / fmaxf(sqrtf(ss0), 1e-12f);
        float inv1 = 1.0f / fmaxf(sqrtf(ss1), 1e-12f);

        acc[0] += a0.x*inv0 + a1.x*inv1;
        acc[1] += a0.y*inv0 + a1.y*inv1;
        acc[2] += a0.z*inv0 + a1.z*inv1;
        acc[3] += a0.w*inv0 + a1.w*inv1;
        acc[4] += b0.x*inv0 + b1.x*inv1;
        acc[5] += b0.y*inv0 + b1.y*inv1;
        acc[6] += b0.z*inv0 + b1.z*inv1;
        acc[7] += b0.w*inv0 + b1.w*inv1;
    }
    // tail: remaining rows (at most one per warp per pass)
    for (; r < cnt; r += 8) {
        int row = __ldg(g_order + start + r);
        const float4* rp = reinterpret_cast<const float4*>(features + (size_t)row * FEAT_DIM);
        float4 a = __ldg(rp + lane * 2);
        float4 b = __ldg(rp + lane * 2 + 1);
        float ss = a.x*a.x + a.y*a.y + a.z*a.z + a.w*a.w
                 + b.x*b.x + b.y*b.y + b.z*b.z + b.w*b.w;
        #pragma unroll
        for (int off = 16; off > 0; off >>= 1)
            ss += __shfl_xor_sync(0xFFFFFFFFu, ss, off);
        float inv = 1.0f / fmaxf(sqrtf(ss), 1e-12f);
        acc[0] += a.x*inv; acc[1] += a.y*inv; acc[2] += a.z*inv; acc[3] += a.w*inv;
        acc[4] += b.x*inv; acc[5] += b.y*inv; acc[6] += b.z*inv; acc[7] += b.w*inv;
    }

    // combine 8 warps via smem
    __shared__ float sh[8 * FEAT_DIM];   // 8 KB
    #pragma unroll
    for (int k = 0; k < 8; k++)
        sh[warp * FEAT_DIM + lane * 8 + k] = acc[k];
    __syncthreads();

    int d = threadIdx.x;                 // 0..255
    float s = 0.f;
    #pragma unroll
    for (int w = 0; w < 8; w++)
        s += sh[w * FEAT_DIM + d];

    // fused prototype EMA
    float stepf    = step_ptr ? (float)__ldg(step_ptr) : 5000.0f;
    float progress = fminf(1.0f, stepf / 2000.0f);       // WARMUP_STEPS*10
    float m        = 0.99f + (0.999f - 0.99f) * progress;

    bool  present = cnt > 0;
    bool  inited  = __ldg(init_mask + c) > 0;
    float mean    = s / fmaxf((float)cnt, 1.0f);
    float p       = __ldg(prototypes + c * FEAT_DIM + d);

    float val;
    if (present && inited)  val = m * p + (1.0f - m) * mean;
    else if (present)       val = mean;
    else                    val = p;

    out_protos[c * FEAT_DIM + d] = val;
    if (d == 0) out_init[c] = (inited || present) ? 1.0f : 0.0f;
}

// ---------------- K4: co-occurrence via popcount of bitmasks ----------------
__global__ void cooc_kernel(const float* __restrict__ cooc_in,
                            float*       __restrict__ cooc_out) {
    int idx = blockIdx.x * blockDim.x + threadIdx.x;
    if (idx >= NUM_CLASSES * NUM_CLASSES) return;
    int i = idx / NUM_CLASSES;
    int j = idx - i * NUM_CLASSES;
    float add = (i == j) ? 0.0f
              : (float)__popcll(__ldg(&g_mask[i]) & __ldg(&g_mask[j]));
    cooc_out[idx] = __ldg(cooc_in + idx) + add;
}

// ---------------- launch ----------------
extern "C" void kernel_launch(void* const* d_in, const int* in_sizes, int n_in,
                              void* d_out, int out_size) {
    const float* features  = (const float*)d_in[0];
    const int*   labels    = (const int*)  d_in[1];
    const int*   lpi       = (const int*)  d_in[2];
    const float* protos    = (const float*)d_in[3];
    const int*   init_mask = (const int*)  d_in[4];
    const float* cooc_in   = (const float*)d_in[5];
    const int*   step_ptr  = (n_in > 6) ? (const int*)d_in[6] : nullptr;

    int n_rows  = in_sizes[1];   // 200000
    int n_lpi   = in_sizes[2];   // 6400

    float* out        = (float*)d_out;
    float* out_protos = out;                                          // 256000
    float* out_init   = out + NUM_CLASSES * FEAT_DIM;                 // 1000
    float* out_cooc   = out + NUM_CLASSES * FEAT_DIM + NUM_CLASSES;   // 1000000

    zero_scratch_kernel<<<(NUM_CLASSES + 255) / 256, 256>>>();
    hist_kernel<<<256, 256>>>(labels, n_rows);
    scan_kernel<<<1, 1024>>>();
    scatter_kernel<<<(n_rows + 255) / 256, 256>>>(labels, n_rows);
    build_mask_kernel<<<(n_lpi + 255) / 256, 256>>>(lpi, n_lpi);
    class_reduce_kernel<<<NUM_CLASSES, 256>>>(features, protos, init_mask, step_ptr,
                                              out_protos, out_init);
    cooc_kernel<<<(NUM_CLASSES * NUM_CLASSES + 255) / 256, 256>>>(cooc_in, out_cooc);
}